// round 15
// baseline (speedup 1.0000x reference)
#include <cuda_runtime.h>
#include <cuda_fp16.h>

#define NN   50000
#define EE   1600000
#define DIN  128
#define DOUT 64
#define CAP  128          // bucket capacity per node (mean deg 32, +17 sigma)

// Scratch (static device globals: allocation-free, allowed)
__device__ __align__(16) __half g_x[3][NN * DOUT];          // fp16 (h @ W_h) * rsqrt(deg_out_h)
__device__ int g_cnt[6][NN];                                 // [0..2]=deg_out, [3..5]=deg_in cursor
__device__ __align__(16) unsigned short g_bkt[3][NN * CAP];  // bucketed CSR: node n at n*CAP

// Side stream + fork/join events, created once at module load.
static cudaStream_t g_s1;
static cudaEvent_t g_evD, g_evB;
namespace {
struct StreamInit {
    StreamInit() {
        cudaStreamCreateWithFlags(&g_s1, cudaStreamNonBlocking);
        cudaEventCreateWithFlags(&g_evD, cudaEventDisableTiming);
        cudaEventCreateWithFlags(&g_evB, cudaEventDisableTiming);
    }
};
StreamInit g_stream_init;
}

// ---------------------------------------------------------------------------
// deg_out histograms only (RED, no return). Runs ALONE (full LTS).
// ---------------------------------------------------------------------------
__global__ void degout_kernel(const int* __restrict__ s0,
                              const int* __restrict__ s1,
                              const int* __restrict__ s2) {
    int i = blockIdx.x * blockDim.x + threadIdx.x;
    if (i >= EE) return;
    atomicAdd(&g_cnt[0][s0[i]], 1);
    atomicAdd(&g_cnt[1][s1[i]], 1);
    atomicAdd(&g_cnt[2][s2[i]], 1);
}

// ---------------------------------------------------------------------------
// Bucket build (LTS-bound) — runs concurrent with gemm (FMA-bound).
// pos = deg_in[d]++ (ATOM), bucket store. grid.y = head.
// ---------------------------------------------------------------------------
__global__ void bucket_kernel(const int* __restrict__ s0, const int* __restrict__ d0,
                              const int* __restrict__ s1, const int* __restrict__ d1,
                              const int* __restrict__ s2, const int* __restrict__ d2) {
    const int h = blockIdx.y;
    const int* s = (h == 0) ? s0 : (h == 1) ? s1 : s2;
    const int* d = (h == 0) ? d0 : (h == 1) ? d1 : d2;
    int e = blockIdx.x * blockDim.x + threadIdx.x;
    if (e >= EE) return;
    int ss = s[e];
    int dd = d[e];
    int pos = atomicAdd(&g_cnt[3 + h][dd], 1);   // deg_in cursor
    pos = min(pos, CAP - 1);                     // statistically impossible; OOB guard
    g_bkt[h][(dd << 7) + pos] = (unsigned short)ss;
}

// ---------------------------------------------------------------------------
// Fused 3-head GEMM with packed f32x2 FMA (FFMA2: 2 fp32 FMA per issue).
// x_h = fp16( (h @ W_h) * rsqrt(max(deg_out_h,1)) )
// ---------------------------------------------------------------------------
__global__ void gemm_kernel(const float* __restrict__ h,
                            const float* __restrict__ W0,
                            const float* __restrict__ W1,
                            const float* __restrict__ W2) {
    __shared__ float Hs[64][130];
    __shared__ float Ws[3][16 * DOUT];

    const int t = threadIdx.x;
    const int rowbase = blockIdx.x * 64;

    #pragma unroll
    for (int j = 0; j < 8; j++) {
        int idx = t + j * 256;
        int r = idx >> 5;
        int kq = idx & 31;
        int row = rowbase + r;
        float4 v = make_float4(0.f, 0.f, 0.f, 0.f);
        if (row < NN) v = ((const float4*)(h + (size_t)row * DIN))[kq];
        Hs[r][kq * 4 + 0] = v.x;
        Hs[r][kq * 4 + 1] = v.y;
        Hs[r][kq * 4 + 2] = v.z;
        Hs[r][kq * 4 + 3] = v.w;
    }

    const int tx = t & 15;
    const int ty = t >> 4;

    unsigned long long acc[3][4][2] = {};

    for (int ko = 0; ko < 8; ko++) {
        __syncthreads();
        ((float4*)Ws[0])[t] = ((const float4*)(W0 + ko * 16 * DOUT))[t];
        ((float4*)Ws[1])[t] = ((const float4*)(W1 + ko * 16 * DOUT))[t];
        ((float4*)Ws[2])[t] = ((const float4*)(W2 + ko * 16 * DOUT))[t];
        __syncthreads();

        #pragma unroll
        for (int ki = 0; ki < 16; ki++) {
            const int kk = ko * 16 + ki;
            float a0 = Hs[ty * 4 + 0][kk];
            float a1 = Hs[ty * 4 + 1][kk];
            float a2 = Hs[ty * 4 + 2][kk];
            float a3 = Hs[ty * 4 + 3][kk];
            unsigned long long pa[4];
            asm("mov.b64 %0, {%1, %1};" : "=l"(pa[0]) : "f"(a0));
            asm("mov.b64 %0, {%1, %1};" : "=l"(pa[1]) : "f"(a1));
            asm("mov.b64 %0, {%1, %1};" : "=l"(pa[2]) : "f"(a2));
            asm("mov.b64 %0, {%1, %1};" : "=l"(pa[3]) : "f"(a3));

            #pragma unroll
            for (int hh = 0; hh < 3; hh++) {
                float4 bv = *(const float4*)&Ws[hh][ki * DOUT + tx * 4];
                unsigned long long pb0, pb1;
                asm("mov.b64 %0, {%1, %2};" : "=l"(pb0) : "f"(bv.x), "f"(bv.y));
                asm("mov.b64 %0, {%1, %2};" : "=l"(pb1) : "f"(bv.z), "f"(bv.w));
                #pragma unroll
                for (int r = 0; r < 4; r++) {
                    asm("fma.rn.f32x2 %0, %1, %2, %0;" : "+l"(acc[hh][r][0]) : "l"(pa[r]), "l"(pb0));
                    asm("fma.rn.f32x2 %0, %1, %2, %0;" : "+l"(acc[hh][r][1]) : "l"(pa[r]), "l"(pb1));
                }
            }
        }
    }

    #pragma unroll
    for (int hh = 0; hh < 3; hh++) {
        __half* xh = g_x[hh];
        #pragma unroll
        for (int r = 0; r < 4; r++) {
            int row = rowbase + ty * 4 + r;
            if (row < NN) {
                float s = rsqrtf(fmaxf((float)g_cnt[hh][row], 1.0f));
                float c0, c1, c2, c3;
                asm("mov.b64 {%0, %1}, %2;" : "=f"(c0), "=f"(c1) : "l"(acc[hh][r][0]));
                asm("mov.b64 {%0, %1}, %2;" : "=f"(c2), "=f"(c3) : "l"(acc[hh][r][1]));
                __half2 p0 = __floats2half2_rn(c0 * s, c1 * s);
                __half2 p1 = __floats2half2_rn(c2 * s, c3 * s);
                uint2 pk;
                pk.x = *(unsigned int*)&p0;
                pk.y = *(unsigned int*)&p1;
                *(uint2*)&xh[row * DOUT + tx * 4] = pk;
            }
        }
    }
}

// ---------------------------------------------------------------------------
// Pull SpMM, warp per dst node. Chunk-of-8 fp16 tree reduction:
// 7 HADD2 + 1 cvt-pair + 2 FADD per 8 edges (vs 16 cvt + 16 FADD) -> ~3.4
// issues/edge. Cross-chunk accumulation fp32; tail (<8) fp32 scalar.
// ---------------------------------------------------------------------------
__global__ void pull_kernel(const float* __restrict__ b0,
                            const float* __restrict__ b1,
                            const float* __restrict__ b2,
                            float* __restrict__ out) {
    const int tid = blockIdx.x * blockDim.x + threadIdx.x;
    int n = tid >> 5;
    if (n >= NN) return;
    const int lane = threadIdx.x & 31;

    float rx = 0.f, ry = 0.f;

    #pragma unroll
    for (int h = 0; h < 3; h++) {
        const __half* xh = g_x[h];
        const unsigned short* row = g_bkt[h] + (n << 7);
        const int cnt = g_cnt[3 + h][n];

        float ax = 0.f, ay = 0.f;

        int j = 0;
        for (; j + 8 <= cnt; j += 8) {
            int i0 = row[j + 0], i1 = row[j + 1], i2 = row[j + 2], i3 = row[j + 3];
            int i4 = row[j + 4], i5 = row[j + 5], i6 = row[j + 6], i7 = row[j + 7];
            __half2 v0 = *(const __half2*)(xh + i0 * DOUT + lane * 2);
            __half2 v1 = *(const __half2*)(xh + i1 * DOUT + lane * 2);
            __half2 v2 = *(const __half2*)(xh + i2 * DOUT + lane * 2);
            __half2 v3 = *(const __half2*)(xh + i3 * DOUT + lane * 2);
            __half2 v4 = *(const __half2*)(xh + i4 * DOUT + lane * 2);
            __half2 v5 = *(const __half2*)(xh + i5 * DOUT + lane * 2);
            __half2 v6 = *(const __half2*)(xh + i6 * DOUT + lane * 2);
            __half2 v7 = *(const __half2*)(xh + i7 * DOUT + lane * 2);
            __half2 t01 = __hadd2(v0, v1);
            __half2 t23 = __hadd2(v2, v3);
            __half2 t45 = __hadd2(v4, v5);
            __half2 t67 = __hadd2(v6, v7);
            __half2 u0 = __hadd2(t01, t23);
            __half2 u1 = __hadd2(t45, t67);
            __half2 s8 = __hadd2(u0, u1);
            float2 f = __half22float2(s8);
            ax += f.x;
            ay += f.y;
        }
        for (; j < cnt; j++) {
            int s = row[j];
            float2 f = __half22float2(*(const __half2*)(xh + s * DOUT + lane * 2));
            ax += f.x;
            ay += f.y;
        }

        float scale = rsqrtf(fmaxf((float)cnt, 1.0f));
        const float* bb = (h == 0) ? b0 : (h == 1) ? b1 : b2;
        rx += fmaxf(ax * scale + bb[lane * 2 + 0], 0.f);
        ry += fmaxf(ay * scale + bb[lane * 2 + 1], 0.f);
    }

    const float third = 1.0f / 3.0f;
    float2 o = make_float2(rx * third, ry * third);
    *(float2*)(out + n * DOUT + lane * 2) = o;
}

// ---------------------------------------------------------------------------
// metadata.txt order:
//   0:h  1:src0 2:dst0 3:W0 4:b0  5:src1 6:dst1 7:W1 8:b1  9:src2 10:dst2 11:W2 12:b2
// Graph:
//   stream0: memset(g_cnt) -> degout -> evD -> gemm -> wait(evB) -> pull
//   s1:      wait(evD) -> bucket -> evB
// (degout runs alone at full LTS; bucket [LTS-bound] overlaps gemm [FMA-bound])
// ---------------------------------------------------------------------------
extern "C" void kernel_launch(void* const* d_in, const int* in_sizes, int n_in,
                              void* d_out, int out_size) {
    const float* h  = (const float*)d_in[0];
    const int*   s0 = (const int*)d_in[1];
    const int*   d0 = (const int*)d_in[2];
    const float* W0 = (const float*)d_in[3];
    const float* b0 = (const float*)d_in[4];
    const int*   s1 = (const int*)d_in[5];
    const int*   d1 = (const int*)d_in[6];
    const float* W1 = (const float*)d_in[7];
    const float* b1 = (const float*)d_in[8];
    const int*   s2 = (const int*)d_in[9];
    const int*   d2 = (const int*)d_in[10];
    const float* W2 = (const float*)d_in[11];
    const float* b2 = (const float*)d_in[12];
    float* out = (float*)d_out;

    void* cntp = nullptr;
    cudaGetSymbolAddress(&cntp, g_cnt);
    cudaMemsetAsync(cntp, 0, sizeof(int) * 6 * NN, 0);

    const int eblocks = (EE + 255) / 256;   // 6250

    degout_kernel<<<eblocks, 256>>>(s0, s1, s2);

    // fork after degout: bucket on side stream, concurrent with gemm
    cudaEventRecord(g_evD, 0);
    cudaStreamWaitEvent(g_s1, g_evD, 0);
    bucket_kernel<<<dim3(eblocks, 3), 256, 0, g_s1>>>(s0, d0, s1, d1, s2, d2);
    cudaEventRecord(g_evB, g_s1);

    gemm_kernel<<<(NN + 63) / 64, 256>>>(h, W0, W1, W2);

    // join: pull needs buckets + cursors + x
    cudaStreamWaitEvent(0, g_evB, 0);
    pull_kernel<<<(NN * 32 + 255) / 256, 256>>>(b0, b1, b2, out);
}

// round 17
// speedup vs baseline: 1.0095x; 1.0095x over previous
#include <cuda_runtime.h>
#include <cuda_fp16.h>

#define NN   50000
#define EE   1600000
#define DIN  128
#define DOUT 64
#define CAP  128          // bucket capacity per node (mean deg 32, +17 sigma)

// Scratch (static device globals: allocation-free, allowed)
__device__ __align__(16) __half g_x[3][NN * DOUT];          // fp16 (h @ W_h) * rsqrt(deg_out_h)
__device__ int g_cnt[6][NN];                                 // [0..2]=deg_out, [3..5]=deg_in cursor
__device__ __align__(16) unsigned short g_bkt[3][NN * CAP];  // bucketed CSR: node n at n*CAP

// ---------------------------------------------------------------------------
// Fused degree + bucket build, 4 edges per thread (int4 index loads, 4
// independent RED + 4 independent ATOM in flight before dependent stores).
// grid.y = head. EE % 4 == 0.
// ---------------------------------------------------------------------------
__global__ void build_kernel(const int* __restrict__ s0, const int* __restrict__ d0,
                             const int* __restrict__ s1, const int* __restrict__ d1,
                             const int* __restrict__ s2, const int* __restrict__ d2) {
    const int h = blockIdx.y;
    const int* s = (h == 0) ? s0 : (h == 1) ? s1 : s2;
    const int* d = (h == 0) ? d0 : (h == 1) ? d1 : d2;
    int q = blockIdx.x * blockDim.x + threadIdx.x;
    if (q >= EE / 4) return;

    int4 ss = ((const int4*)s)[q];
    int4 dd = ((const int4*)d)[q];

    // deg_out (no return -> RED), 4 independent
    atomicAdd(&g_cnt[h][ss.x], 1);
    atomicAdd(&g_cnt[h][ss.y], 1);
    atomicAdd(&g_cnt[h][ss.z], 1);
    atomicAdd(&g_cnt[h][ss.w], 1);

    // deg_in cursors, 4 independent ATOMs issue before any store consumes
    int p0 = atomicAdd(&g_cnt[3 + h][dd.x], 1);
    int p1 = atomicAdd(&g_cnt[3 + h][dd.y], 1);
    int p2 = atomicAdd(&g_cnt[3 + h][dd.z], 1);
    int p3 = atomicAdd(&g_cnt[3 + h][dd.w], 1);

    p0 = min(p0, CAP - 1);   // statistically impossible; OOB guard
    p1 = min(p1, CAP - 1);
    p2 = min(p2, CAP - 1);
    p3 = min(p3, CAP - 1);

    g_bkt[h][(dd.x << 7) + p0] = (unsigned short)ss.x;
    g_bkt[h][(dd.y << 7) + p1] = (unsigned short)ss.y;
    g_bkt[h][(dd.z << 7) + p2] = (unsigned short)ss.z;
    g_bkt[h][(dd.w << 7) + p3] = (unsigned short)ss.w;
}

// ---------------------------------------------------------------------------
// Fused 3-head GEMM with packed f32x2 FMA (FFMA2: 2 fp32 FMA per issue).
// x_h = fp16( (h @ W_h) * rsqrt(max(deg_out_h,1)) )
// ---------------------------------------------------------------------------
__global__ void gemm_kernel(const float* __restrict__ h,
                            const float* __restrict__ W0,
                            const float* __restrict__ W1,
                            const float* __restrict__ W2) {
    __shared__ float Hs[64][130];
    __shared__ float Ws[3][16 * DOUT];

    const int t = threadIdx.x;
    const int rowbase = blockIdx.x * 64;

    #pragma unroll
    for (int j = 0; j < 8; j++) {
        int idx = t + j * 256;
        int r = idx >> 5;
        int kq = idx & 31;
        int row = rowbase + r;
        float4 v = make_float4(0.f, 0.f, 0.f, 0.f);
        if (row < NN) v = ((const float4*)(h + (size_t)row * DIN))[kq];
        Hs[r][kq * 4 + 0] = v.x;
        Hs[r][kq * 4 + 1] = v.y;
        Hs[r][kq * 4 + 2] = v.z;
        Hs[r][kq * 4 + 3] = v.w;
    }

    const int tx = t & 15;
    const int ty = t >> 4;

    unsigned long long acc[3][4][2] = {};

    for (int ko = 0; ko < 8; ko++) {
        __syncthreads();
        ((float4*)Ws[0])[t] = ((const float4*)(W0 + ko * 16 * DOUT))[t];
        ((float4*)Ws[1])[t] = ((const float4*)(W1 + ko * 16 * DOUT))[t];
        ((float4*)Ws[2])[t] = ((const float4*)(W2 + ko * 16 * DOUT))[t];
        __syncthreads();

        #pragma unroll
        for (int ki = 0; ki < 16; ki++) {
            const int kk = ko * 16 + ki;
            float a0 = Hs[ty * 4 + 0][kk];
            float a1 = Hs[ty * 4 + 1][kk];
            float a2 = Hs[ty * 4 + 2][kk];
            float a3 = Hs[ty * 4 + 3][kk];
            unsigned long long pa[4];
            asm("mov.b64 %0, {%1, %1};" : "=l"(pa[0]) : "f"(a0));
            asm("mov.b64 %0, {%1, %1};" : "=l"(pa[1]) : "f"(a1));
            asm("mov.b64 %0, {%1, %1};" : "=l"(pa[2]) : "f"(a2));
            asm("mov.b64 %0, {%1, %1};" : "=l"(pa[3]) : "f"(a3));

            #pragma unroll
            for (int hh = 0; hh < 3; hh++) {
                float4 bv = *(const float4*)&Ws[hh][ki * DOUT + tx * 4];
                unsigned long long pb0, pb1;
                asm("mov.b64 %0, {%1, %2};" : "=l"(pb0) : "f"(bv.x), "f"(bv.y));
                asm("mov.b64 %0, {%1, %2};" : "=l"(pb1) : "f"(bv.z), "f"(bv.w));
                #pragma unroll
                for (int r = 0; r < 4; r++) {
                    asm("fma.rn.f32x2 %0, %1, %2, %0;" : "+l"(acc[hh][r][0]) : "l"(pa[r]), "l"(pb0));
                    asm("fma.rn.f32x2 %0, %1, %2, %0;" : "+l"(acc[hh][r][1]) : "l"(pa[r]), "l"(pb1));
                }
            }
        }
    }

    #pragma unroll
    for (int hh = 0; hh < 3; hh++) {
        __half* xh = g_x[hh];
        #pragma unroll
        for (int r = 0; r < 4; r++) {
            int row = rowbase + ty * 4 + r;
            if (row < NN) {
                float s = rsqrtf(fmaxf((float)g_cnt[hh][row], 1.0f));
                float c0, c1, c2, c3;
                asm("mov.b64 {%0, %1}, %2;" : "=f"(c0), "=f"(c1) : "l"(acc[hh][r][0]));
                asm("mov.b64 {%0, %1}, %2;" : "=f"(c2), "=f"(c3) : "l"(acc[hh][r][1]));
                __half2 p0 = __floats2half2_rn(c0 * s, c1 * s);
                __half2 p1 = __floats2half2_rn(c2 * s, c3 * s);
                uint2 pk;
                pk.x = *(unsigned int*)&p0;
                pk.y = *(unsigned int*)&p1;
                *(uint2*)&xh[row * DOUT + tx * 4] = pk;
            }
        }
    }
}

// ---------------------------------------------------------------------------
// Pull SpMM, warp per dst node, 8-deep unroll, fp32 accumulation, scalar tail
// (<=7, no inner ifs). Bucket row n at g_bkt[h] + (n<<7), cnt = g_cnt[3+h][n].
// ---------------------------------------------------------------------------
__global__ void pull_kernel(const float* __restrict__ b0,
                            const float* __restrict__ b1,
                            const float* __restrict__ b2,
                            float* __restrict__ out) {
    const int tid = blockIdx.x * blockDim.x + threadIdx.x;
    int n = tid >> 5;
    if (n >= NN) return;
    const int lane = threadIdx.x & 31;

    float rx = 0.f, ry = 0.f;

    #pragma unroll
    for (int h = 0; h < 3; h++) {
        const __half* xh = g_x[h];
        const unsigned short* row = g_bkt[h] + (n << 7);
        const int cnt = g_cnt[3 + h][n];

        float ax0 = 0.f, ay0 = 0.f, ax1 = 0.f, ay1 = 0.f;

        int j = 0;
        for (; j + 8 <= cnt; j += 8) {
            int i0 = row[j + 0], i1 = row[j + 1], i2 = row[j + 2], i3 = row[j + 3];
            int i4 = row[j + 4], i5 = row[j + 5], i6 = row[j + 6], i7 = row[j + 7];
            float2 f0 = __half22float2(*(const __half2*)(xh + i0 * DOUT + lane * 2));
            float2 f1 = __half22float2(*(const __half2*)(xh + i1 * DOUT + lane * 2));
            float2 f2 = __half22float2(*(const __half2*)(xh + i2 * DOUT + lane * 2));
            float2 f3 = __half22float2(*(const __half2*)(xh + i3 * DOUT + lane * 2));
            float2 f4 = __half22float2(*(const __half2*)(xh + i4 * DOUT + lane * 2));
            float2 f5 = __half22float2(*(const __half2*)(xh + i5 * DOUT + lane * 2));
            float2 f6 = __half22float2(*(const __half2*)(xh + i6 * DOUT + lane * 2));
            float2 f7 = __half22float2(*(const __half2*)(xh + i7 * DOUT + lane * 2));
            ax0 += (f0.x + f1.x) + (f2.x + f3.x);
            ay0 += (f0.y + f1.y) + (f2.y + f3.y);
            ax1 += (f4.x + f5.x) + (f6.x + f7.x);
            ay1 += (f4.y + f5.y) + (f6.y + f7.y);
        }
        for (; j < cnt; j++) {
            int s = row[j];
            float2 f = __half22float2(*(const __half2*)(xh + s * DOUT + lane * 2));
            ax0 += f.x;
            ay0 += f.y;
        }

        float ax = ax0 + ax1;
        float ay = ay0 + ay1;
        float scale = rsqrtf(fmaxf((float)cnt, 1.0f));
        const float* bb = (h == 0) ? b0 : (h == 1) ? b1 : b2;
        rx += fmaxf(ax * scale + bb[lane * 2 + 0], 0.f);
        ry += fmaxf(ay * scale + bb[lane * 2 + 1], 0.f);
    }

    const float third = 1.0f / 3.0f;
    float2 o = make_float2(rx * third, ry * third);
    *(float2*)(out + n * DOUT + lane * 2) = o;
}

// ---------------------------------------------------------------------------
// metadata.txt order:
//   0:h  1:src0 2:dst0 3:W0 4:b0  5:src1 6:dst1 7:W1 8:b1  9:src2 10:dst2 11:W2 12:b2
// Launch order (single stream): memset(g_cnt), build, gemm, pull
// ---------------------------------------------------------------------------
extern "C" void kernel_launch(void* const* d_in, const int* in_sizes, int n_in,
                              void* d_out, int out_size) {
    const float* h  = (const float*)d_in[0];
    const int*   s0 = (const int*)d_in[1];
    const int*   d0 = (const int*)d_in[2];
    const float* W0 = (const float*)d_in[3];
    const float* b0 = (const float*)d_in[4];
    const int*   s1 = (const int*)d_in[5];
    const int*   d1 = (const int*)d_in[6];
    const float* W1 = (const float*)d_in[7];
    const float* b1 = (const float*)d_in[8];
    const int*   s2 = (const int*)d_in[9];
    const int*   d2 = (const int*)d_in[10];
    const float* W2 = (const float*)d_in[11];
    const float* b2 = (const float*)d_in[12];
    float* out = (float*)d_out;

    void* cntp = nullptr;
    cudaGetSymbolAddress(&cntp, g_cnt);
    cudaMemsetAsync(cntp, 0, sizeof(int) * 6 * NN, 0);

    const int qblocks = (EE / 4 + 255) / 256;   // 1563

    build_kernel<<<dim3(qblocks, 3), 256>>>(s0, d0, s1, d1, s2, d2);

    gemm_kernel<<<(NN + 63) / 64, 256>>>(h, W0, W1, W2);

    pull_kernel<<<(NN * 32 + 255) / 256, 256>>>(b0, b1, b2, out);
}